// round 13
// baseline (speedup 1.0000x reference)
#include <cuda_runtime.h>
#include <cstdint>

// y[n,j,h,w] = sum_{k,c} s[w+k][c] * wgt[j,k,c];  out[n,j,(h+1)%56,w] = y
//   s[u][c]: u==0||u==57 -> 0 ; u==1 -> x[...,55] (W-roll wrap) ; else x[...,u-2]
// Per tile (n, h-pair): D[128 m, 32 j] = A[128,384]*B[32,384]^T via mma.m16n8k32.s8.
// Two-level int8 quantization: v = (8/127)*(q1 + q2/254); passes P1=a1b1,
// PL=a2b1+a1b2; y = S^2*(P1 + PL/254); dropped a2b2 ~3.4e-4 rel (norm).
// 768 threads / 24 warps: warps 0-15 consumers in 8 k-split pairs (16m x 32j,
// 6 k32-steps each); warps 16-23 producers (LDG -> quantize -> STS.16 into
// double-buffered int8 T). mbarrier handoff, consumers release T after last ldsm.

#define NT      3584
#define NCTA    148
#define THREADS 768

#define SM_W1   0u          // W level-1 int8: [j][384], 384B rows, seg-swizzled
#define SM_W2   12288u
#define SM_T0A  24576u      // A int8: [hs][64 u][128 c], 128B rows, seg-swizzled, 16KB
#define SM_T0B  40960u
#define SM_T1A  57344u
#define SM_T1B  73728u
#define SM_RED  90112u      // 2 parities x 8 pairs x 4KB (int32 partial sums)
#define SM_BARS 155648u
#define SM_TOTAL 155712

static __device__ __forceinline__ uint32_t s2u(const void* p) {
    uint32_t a;
    asm("{ .reg .u64 t; cvta.to.shared.u64 t, %1; cvt.u32.u64 %0, t; }" : "=r"(a) : "l"(p));
    return a;
}
static __device__ __forceinline__ void ldsm4(uint32_t* r, uint32_t addr) {
    asm volatile("ldmatrix.sync.aligned.m8n8.x4.shared.b16 {%0,%1,%2,%3}, [%4];"
                 : "=r"(r[0]), "=r"(r[1]), "=r"(r[2]), "=r"(r[3]) : "r"(addr));
}
static __device__ __forceinline__ void imma16832(int* c, const uint32_t* a, const uint32_t* b) {
    asm volatile("mma.sync.aligned.m16n8k32.row.col.s32.s8.s8.s32 "
                 "{%0,%1,%2,%3}, {%4,%5,%6,%7}, {%8,%9}, {%0,%1,%2,%3};"
                 : "+r"(c[0]), "+r"(c[1]), "+r"(c[2]), "+r"(c[3])
                 : "r"(a[0]), "r"(a[1]), "r"(a[2]), "r"(a[3]), "r"(b[0]), "r"(b[1]));
}
static __device__ __forceinline__ void mbar_init(uint32_t bar, uint32_t cnt) {
    asm volatile("mbarrier.init.shared.b64 [%0], %1;" :: "r"(bar), "r"(cnt) : "memory");
}
static __device__ __forceinline__ void mbar_arrive(uint32_t bar) {
    asm volatile("mbarrier.arrive.shared.b64 _, [%0];" :: "r"(bar) : "memory");
}
static __device__ __forceinline__ void mbar_wait(uint32_t bar, uint32_t parity) {
    asm volatile(
        "{\n\t.reg .pred P;\n\t"
        "W%=:\n\t"
        "mbarrier.try_wait.parity.shared.b64 P, [%0], %1;\n\t"
        "@P bra.uni D%=;\n\t"
        "bra.uni W%=;\n\t"
        "D%=:\n\t}" :: "r"(bar), "r"(parity) : "memory");
}
// two-level int8 quantization of v (|v| < 8): v ~= (8/127)*(q1 + q2/254)
static __device__ __forceinline__ void quant2(float v, int& q1, int& q2) {
    float f = v * 15.875f;               // 127/8
    q1 = __float2int_rn(f);
    q2 = __float2int_rn((f - (float)q1) * 254.0f);
}

// Produce one tile: x (global) -> TA1/TA2 int8 slabs, roll+pad folded into row u.
static __device__ __forceinline__ void produce_tile(const float* __restrict__ x,
                                                    char* smem, uint32_t dA1, uint32_t dA2,
                                                    int n, int hp, int warp0, int nwarps,
                                                    int lane) {
    const int cpl = lane >> 1;
    const int wc  = lane & 1;
    #pragma unroll 4
    for (int task = warp0; task < 56; task += nwarps) {
        const int hs  = task / 28;
        const int r   = task % 28;
        const int cpg = r / 7;
        const int wp  = r % 7;
        const int c   = cpg * 32 + cpl * 2;
        const int w0  = wp * 8 + wc * 4;
        const float* src = x + ((size_t)(n * 128 + c) * 56 + hp * 2 + hs) * 56 + w0;
        const float4 va = *(const float4*)src;
        const float4 vb = *(const float4*)(src + 3136);
        const float fa[4] = {va.x, va.y, va.z, va.w};
        const float fb[4] = {vb.x, vb.y, vb.z, vb.w};
        const uint32_t segsw = (uint32_t)(c >> 4);
        const uint32_t cbyte = (uint32_t)(c & 15);
        #pragma unroll
        for (int i = 0; i < 4; i++) {
            const int w = w0 + i;
            const int u = (w == 55) ? 1 : (w + 2);
            int a1, a2, b1, b2;
            quant2(fa[i], a1, a2);
            quant2(fb[i], b1, b2);
            uint16_t h1 = (uint16_t)((a1 & 0xFF) | ((b1 & 0xFF) << 8));
            uint16_t h2 = (uint16_t)((a2 & 0xFF) | ((b2 & 0xFF) << 8));
            uint32_t off = (uint32_t)hs * 8192 + (uint32_t)u * 128
                           + ((segsw ^ (uint32_t)(u & 7)) << 4) + cbyte;
            *(uint16_t*)(smem + dA1 + off) = h1;
            *(uint16_t*)(smem + dA2 + off) = h2;
        }
    }
}

__global__ __launch_bounds__(THREADS, 1)
void shiftconv_i8(const float* __restrict__ x,
                  const float* __restrict__ wsrc,
                  float* __restrict__ out) {
    extern __shared__ char smem[];
    const uint32_t sb = s2u(smem);
    const int tid  = threadIdx.x;
    const int lane = tid & 31;
    const int wid  = tid >> 5;

    // ---- one-time: quantize W to two int8 slabs (seg-swizzled 384B rows) ----
    for (int i = tid; i < 12288; i += THREADS) {
        int j = i / 384, k = i % 384;
        int q1, q2;
        quant2(wsrc[i], q1, q2);
        uint32_t off = (uint32_t)j * 384
                       + ((((uint32_t)(k >> 4)) ^ (uint32_t)(j & 7)) << 4)
                       + (uint32_t)(k & 15);
        *(int8_t*)(smem + SM_W1 + off) = (int8_t)q1;
        *(int8_t*)(smem + SM_W2 + off) = (int8_t)q2;
    }
    // ---- zero pad rows u in {0, 57..63}, both hs, all 4 T slabs (16KB each) ----
    for (int i = tid; i < 2048; i += THREADS) {
        int slab = i >> 9;
        int rem  = i & 511;
        int hs   = rem >> 8;
        int rw   = (rem >> 5) & 7;
        int u    = (rw == 0) ? 0 : (56 + rw);
        int wd   = rem & 31;
        *(uint32_t*)(smem + SM_T0A + (uint32_t)slab * 16384u + (uint32_t)hs * 8192
                     + (uint32_t)u * 128 + (uint32_t)wd * 4) = 0u;
    }
    // ---- mbarriers: full[b] <- producers (256 thr), empty[b] <- consumers (512 thr)
    const uint32_t barF0 = sb + SM_BARS,      barF1 = sb + SM_BARS + 8;
    const uint32_t barE0 = sb + SM_BARS + 16, barE1 = sb + SM_BARS + 24;
    if (tid == 0) {
        mbar_init(barF0, 256); mbar_init(barF1, 256);
        mbar_init(barE0, 512); mbar_init(barE1, 512);
    }
    __syncthreads();   // W, pad-zero, mbarrier init visible

    const int t0 = blockIdx.x;

    if (wid < 16) {
        // ======= consumers: 8 k-split pairs, each pair = 16m x 32j sub-tile =======
        const int pr   = wid >> 1;            // 0..7 -> m-subtile (16 rows)
        const int kh   = wid & 1;             // k-half (6 k32-steps each)
        const int hsub = pr >> 2;
        const int wm0  = (pr & 3) * 16;
        const int g  = lane >> 2, tg = lane & 3;
        const int al = lane & 15;
        const uint32_t ad = (uint32_t)(lane >> 4);
        const int bj = (lane & 7) + ((lane >> 4) << 3);
        const uint32_t bd   = (uint32_t)((lane >> 3) & 1);
        const uint32_t bj7  = (uint32_t)(bj & 7);
        const uint32_t brow0 = (uint32_t)bj * 384;
        const uint32_t brow1 = (uint32_t)(bj + 16) * 384;
        uint32_t abase[3], amask[3];
        #pragma unroll
        for (int tp = 0; tp < 3; tp++) {
            int u = wm0 + al + tp; if (u > 63) u = 63;
            abase[tp] = (uint32_t)hsub * 8192 + (uint32_t)u * 128;
            amask[tp] = (uint32_t)(u & 7);
        }

        int i = 0;
        for (int tt = t0; tt < NT; tt += NCTA, i++) {
            const int n = tt / 28, hp = tt % 28;
            const int b = i & 1;
            mbar_wait(b ? barF1 : barF0, (uint32_t)((i >> 1) & 1));

            const uint32_t tA1 = sb + (b ? SM_T1A : SM_T0A);
            const uint32_t tA2 = sb + (b ? SM_T1B : SM_T0B);
            int accH[4][4], accL[4][4];
            #pragma unroll
            for (int nt = 0; nt < 4; nt++)
                #pragma unroll
                for (int q = 0; q < 4; q++) { accH[nt][q] = 0; accL[nt][q] = 0; }

            // one k32-step: S in 0..11, tap = S>>2, c-block = S&3
            #define KSTEP(S) do {                                                    \
                const int TP = (S) >> 2;                                             \
                const uint32_t cs = (uint32_t)(((S) & 3) * 2);                       \
                const uint32_t aoff = abase[TP] + (((cs + ad) ^ amask[TP]) << 4);    \
                uint32_t a1[4], a2[4], b1[8], b2[8];                                 \
                ldsm4(a1, tA1 + aoff);                                               \
                ldsm4(a2, tA2 + aoff);                                               \
                const uint32_t bsg = (uint32_t)(TP * 8) + cs + bd;                   \
                const uint32_t bo0 = brow0 + ((bsg ^ bj7) << 4);                     \
                const uint32_t bo1 = brow1 + ((bsg ^ bj7) << 4);                     \
                ldsm4(b1,     sb + SM_W1 + bo0);                                     \
                ldsm4(b1 + 4, sb + SM_W1 + bo1);                                     \
                ldsm4(b2,     sb + SM_W2 + bo0);                                     \
                ldsm4(b2 + 4, sb + SM_W2 + bo1);                                     \
                _Pragma("unroll")                                                    \
                for (int nt = 0; nt < 4; nt++) {                                     \
                    imma16832(accH[nt], a1, b1 + nt * 2);                            \
                    imma16832(accL[nt], a2, b1 + nt * 2);                            \
                    imma16832(accL[nt], a1, b2 + nt * 2);                            \
                }                                                                    \
            } while (0)

            if (kh == 0) { KSTEP(0); KSTEP(1); KSTEP(2);  KSTEP(3);  KSTEP(4);  KSTEP(5); }
            else         { KSTEP(6); KSTEP(7); KSTEP(8);  KSTEP(9);  KSTEP(10); KSTEP(11); }
            #undef KSTEP

            // T reads done -> release buffer so producers refill during epilogue
            mbar_arrive(b ? barE1 : barE0);

            // ---- pair reduction (exact int32, parity-double-buffered 4KB/pair) ----
            char* red = smem + SM_RED + (uint32_t)b * 32768u + (uint32_t)pr * 4096u;
            if (kh == 1) {
                #pragma unroll
                for (int nt = 0; nt < 4; nt++) {
                    *((int4*)red + nt * 32 + lane) =
                        make_int4(accH[nt][0], accH[nt][1], accH[nt][2], accH[nt][3]);
                    *((int4*)red + (nt + 4) * 32 + lane) =
                        make_int4(accL[nt][0], accL[nt][1], accL[nt][2], accL[nt][3]);
                }
                asm volatile("bar.sync %0, 64;" :: "r"(1 + pr) : "memory");
            } else {
                asm volatile("bar.sync %0, 64;" :: "r"(1 + pr) : "memory");
                #pragma unroll
                for (int nt = 0; nt < 4; nt++) {
                    int4 vh = *((int4*)red + nt * 32 + lane);
                    int4 vl = *((int4*)red + (nt + 4) * 32 + lane);
                    accH[nt][0] += vh.x; accH[nt][1] += vh.y;
                    accH[nt][2] += vh.z; accH[nt][3] += vh.w;
                    accL[nt][0] += vl.x; accL[nt][1] += vl.y;
                    accL[nt][2] += vl.z; accL[nt][3] += vl.w;
                }
                // ---- epilogue scale + store with H-roll folded ----
                const float S2  = (8.0f / 127.0f) * (8.0f / 127.0f);
                const float S2L = S2 / 254.0f;
                const int h  = hp * 2 + hsub;
                const int ho = (h + 1) % 56;
                float* ob = out + (size_t)n * 100352 + ho * 56;
                const int row0 = wm0 + g;           // <= 55 always
                const int row1 = row0 + 8;
                #pragma unroll
                for (int nt = 0; nt < 4; nt++) {
                    const int j = nt * 8 + tg * 2;
                    ob[(size_t)j * 3136 + row0] =
                        S2 * (float)accH[nt][0] + S2L * (float)accL[nt][0];
                    ob[(size_t)(j + 1) * 3136 + row0] =
                        S2 * (float)accH[nt][1] + S2L * (float)accL[nt][1];
                    if (row1 < 56) {
                        ob[(size_t)j * 3136 + row1] =
                            S2 * (float)accH[nt][2] + S2L * (float)accL[nt][2];
                        ob[(size_t)(j + 1) * 3136 + row1] =
                            S2 * (float)accH[nt][3] + S2L * (float)accL[nt][3];
                    }
                }
            }
        }
    } else {
        // ================= producers: fill T up to 2 tiles ahead =================
        int i = 0;
        for (int tt = t0; tt < NT; tt += NCTA, i++) {
            const int b = i & 1;
            if (i >= 2)
                mbar_wait(b ? barE1 : barE0, (uint32_t)(((i >> 1) - 1) & 1));
            produce_tile(x, smem,
                         b ? SM_T1A : SM_T0A, b ? SM_T1B : SM_T0B,
                         tt / 28, tt % 28, wid - 16, 8, lane);
            mbar_arrive(b ? barF1 : barF0);
        }
    }
}

extern "C" void kernel_launch(void* const* d_in, const int* in_sizes, int n_in,
                              void* d_out, int out_size) {
    const float* x = (const float*)d_in[0];   // (128,128,56,56)
    const float* w = (const float*)d_in[1];   // (32,3,128)
    float* out = (float*)d_out;               // (128,32,56,56)

    cudaFuncSetAttribute(shiftconv_i8, cudaFuncAttributeMaxDynamicSharedMemorySize, SM_TOTAL);
    shiftconv_i8<<<NCTA, THREADS, SM_TOTAL>>>(x, w, out);
}

// round 14
// speedup vs baseline: 2.0929x; 2.0929x over previous
#include <cuda_runtime.h>
#include <cstdint>

// y[n,j,h,w] = sum_{k,c} s[w+k][c] * wgt[j,k,c];  out[n,j,(h+1)%56,w] = y
//   s[u][c]: u==0||u==57 -> 0 ; u==1 -> x[...,55] (W-roll wrap) ; else x[...,u-2]
// Per tile (n, h-pair): D[128 m, 32 j] = A[128,384]*B[32,384]^T via mma.sync bf16,
// hi/lo split of BOTH operands, 3 passes: AhBh + AlBh + AhBl (rel ~4.7e-6).
// 768 threads / 24 warps. Consumers = warps 0-15 in 4 GROUPS of 4: group owns a
// 32m x 32j sub-tile, warp q of group covers 6 of 24 k-steps (4-way k-split);
// per k-step: 4 B-ldsm shared across both 16m halves (8 ldsm : 24 mma).
// In-group 2-stage smem tree reduction. Producers = warps 16-23 fill
// double-buffered T; mbarrier handoff, consumers release T after last ldsm.

#define NT      3584
#define NCTA    148
#define THREADS 768

#define SM_WHI  0u          // W hi bf16: [j][384], 768B rows, seg-swizzled
#define SM_WLO  24576u
#define SM_T0H  49152u      // A bf16: [hs][64 u][128 c], 256B rows, seg-swizzled, 32KB
#define SM_T0L  81920u
#define SM_T1H  114688u
#define SM_T1L  147456u
#define SM_RED  180224u     // 4 groups x 2 x 4KB tree-reduction buffers
#define SM_BARS 212992u     // full[2], empty[2] mbarriers
#define SM_TOTAL 213056

static __device__ __forceinline__ uint32_t s2u(const void* p) {
    uint32_t a;
    asm("{ .reg .u64 t; cvta.to.shared.u64 t, %1; cvt.u32.u64 %0, t; }" : "=r"(a) : "l"(p));
    return a;
}
// packed bf16x2: low half <- lo, high half <- hi
static __device__ __forceinline__ uint32_t bf2(float lo, float hi) {
    uint32_t r;
    asm("cvt.rn.bf16x2.f32 %0, %1, %2;" : "=r"(r) : "f"(hi), "f"(lo));
    return r;
}
static __device__ __forceinline__ void ldsm4(uint32_t* r, uint32_t addr) {
    asm volatile("ldmatrix.sync.aligned.m8n8.x4.shared.b16 {%0,%1,%2,%3}, [%4];"
                 : "=r"(r[0]), "=r"(r[1]), "=r"(r[2]), "=r"(r[3]) : "r"(addr));
}
static __device__ __forceinline__ void mma16816(float* c, const uint32_t* a, const uint32_t* b) {
    asm volatile("mma.sync.aligned.m16n8k16.row.col.f32.bf16.bf16.f32 "
                 "{%0,%1,%2,%3}, {%4,%5,%6,%7}, {%8,%9}, {%0,%1,%2,%3};"
                 : "+f"(c[0]), "+f"(c[1]), "+f"(c[2]), "+f"(c[3])
                 : "r"(a[0]), "r"(a[1]), "r"(a[2]), "r"(a[3]), "r"(b[0]), "r"(b[1]));
}
static __device__ __forceinline__ void mbar_init(uint32_t bar, uint32_t cnt) {
    asm volatile("mbarrier.init.shared.b64 [%0], %1;" :: "r"(bar), "r"(cnt) : "memory");
}
static __device__ __forceinline__ void mbar_arrive(uint32_t bar) {
    asm volatile("mbarrier.arrive.shared.b64 _, [%0];" :: "r"(bar) : "memory");
}
static __device__ __forceinline__ void mbar_wait(uint32_t bar, uint32_t parity) {
    asm volatile(
        "{\n\t.reg .pred P;\n\t"
        "W%=:\n\t"
        "mbarrier.try_wait.parity.shared.b64 P, [%0], %1;\n\t"
        "@P bra.uni D%=;\n\t"
        "bra.uni W%=;\n\t"
        "D%=:\n\t}" :: "r"(bar), "r"(parity) : "memory");
}

// Produce one tile: x (global) -> THI/TLO bf16 slabs, roll+pad folded into row u.
static __device__ __forceinline__ void produce_tile(const float* __restrict__ x,
                                                    char* smem, uint32_t dHI, uint32_t dLO,
                                                    int n, int hp, int warp0, int nwarps,
                                                    int lane) {
    const int cpl = lane >> 1;
    const int wc  = lane & 1;
    #pragma unroll 4
    for (int task = warp0; task < 56; task += nwarps) {
        const int hs  = task / 28;
        const int r   = task % 28;
        const int cpg = r / 7;
        const int wp  = r % 7;
        const int c   = cpg * 32 + cpl * 2;
        const int w0  = wp * 8 + wc * 4;
        const float* src = x + ((size_t)(n * 128 + c) * 56 + hp * 2 + hs) * 56 + w0;
        const float4 va = *(const float4*)src;
        const float4 vb = *(const float4*)(src + 3136);
        const float fa[4] = {va.x, va.y, va.z, va.w};
        const float fb[4] = {vb.x, vb.y, vb.z, vb.w};
        #pragma unroll
        for (int i = 0; i < 4; i++) {
            const int w = w0 + i;
            const int u = (w == 55) ? 1 : (w + 2);
            uint32_t hi = bf2(fa[i], fb[i]);
            float ea = __uint_as_float(hi << 16);
            float eb = __uint_as_float(hi & 0xffff0000u);
            uint32_t lo = bf2(fa[i] - ea, fb[i] - eb);
            uint32_t seg = ((uint32_t)(c >> 3)) ^ (uint32_t)(u & 7);
            uint32_t off = (uint32_t)hs * 16384 + (uint32_t)u * 256
                           + (seg << 4) + ((uint32_t)(c & 7) << 1);
            *(uint32_t*)(smem + dHI + off) = hi;
            *(uint32_t*)(smem + dLO + off) = lo;
        }
    }
}

__global__ __launch_bounds__(THREADS, 1)
void shiftconv_g4(const float* __restrict__ x,
                  const float* __restrict__ wsrc,
                  float* __restrict__ out) {
    extern __shared__ char smem[];
    const uint32_t sb = s2u(smem);
    const int tid  = threadIdx.x;
    const int lane = tid & 31;
    const int wid  = tid >> 5;

    // ---- one-time: W hi/lo bf16 (seg-swizzled) ----
    for (int i = tid; i < 6144; i += THREADS) {
        int j = i / 192, kp = i % 192, k = kp * 2;
        float2 ab = *(const float2*)(wsrc + j * 384 + k);
        uint32_t hi = bf2(ab.x, ab.y);
        float ea = __uint_as_float(hi << 16);
        float eb = __uint_as_float(hi & 0xffff0000u);
        uint32_t lo = bf2(ab.x - ea, ab.y - eb);
        uint32_t seg = ((uint32_t)(k >> 3)) ^ (uint32_t)(j & 7);
        uint32_t off = (uint32_t)j * 768 + (seg << 4) + ((k & 7) << 1);
        *(uint32_t*)(smem + SM_WHI + off) = hi;
        *(uint32_t*)(smem + SM_WLO + off) = lo;
    }
    // ---- zero pad rows u in {0, 57..63}, both hs, all 4 T slabs ----
    for (int i = tid; i < 4096; i += THREADS) {
        int slab = i >> 10;
        int rem  = i & 1023;
        int hs   = rem >> 9;
        int rw   = (rem >> 6) & 7;
        int u    = (rw == 0) ? 0 : (56 + rw);
        int wd   = rem & 63;
        uint32_t base = SM_T0H + (uint32_t)slab * 32768u;
        *(uint32_t*)(smem + base + (uint32_t)hs * 16384 + (uint32_t)u * 256
                     + (uint32_t)wd * 4) = 0u;
    }
    // ---- mbarriers: full[b] <- producers (256 thr), empty[b] <- consumers (512 thr)
    const uint32_t barF0 = sb + SM_BARS,      barF1 = sb + SM_BARS + 8;
    const uint32_t barE0 = sb + SM_BARS + 16, barE1 = sb + SM_BARS + 24;
    if (tid == 0) {
        mbar_init(barF0, 256); mbar_init(barF1, 256);
        mbar_init(barE0, 512); mbar_init(barE1, 512);
    }
    __syncthreads();   // W, pad-zero, mbarrier init visible

    const int t0 = blockIdx.x;

    if (wid < 16) {
        // ==== consumers: 4 groups x 4 warps; group = 32m x 32j; warp = 6 k-steps ====
        const int grp = wid >> 2;             // 0..3 -> m sub-tile (32 rows)
        const int q   = wid & 3;              // k-quarter
        const int hsub = grp >> 1;
        const int wm0  = (grp & 1) * 32;
        const int g  = lane >> 2, tg = lane & 3;
        const int al = lane & 15;
        const uint32_t ad = (uint32_t)(lane >> 4);
        const int bj = (lane & 7) + ((lane >> 4) << 3);
        const uint32_t bd   = (uint32_t)((lane >> 3) & 1);
        const uint32_t bj7  = (uint32_t)(bj & 7);
        const uint32_t brow0 = (uint32_t)bj * 768;
        const uint32_t brow1 = (uint32_t)(bj + 16) * 768;
        uint32_t abase[2][3], amask[2][3];
        #pragma unroll
        for (int mt = 0; mt < 2; mt++)
            #pragma unroll
            for (int tp = 0; tp < 3; tp++) {
                int u = wm0 + mt * 16 + al + tp; if (u > 63) u = 63;
                abase[mt][tp] = (uint32_t)hsub * 16384 + (uint32_t)u * 256;
                amask[mt][tp] = (uint32_t)(u & 7);
            }
        char* red  = smem + SM_RED + (uint32_t)grp * 8192u;
        const int rbar = 1 + grp;

        int i = 0;
        for (int tt = t0; tt < NT; tt += NCTA, i++) {
            const int n = tt / 28, hp = tt % 28;
            const int b = i & 1;
            mbar_wait(b ? barF1 : barF0, (uint32_t)((i >> 1) & 1));

            const uint32_t tHI = sb + (b ? SM_T1H : SM_T0H);
            const uint32_t tLO = sb + (b ? SM_T1L : SM_T0L);
            float acc0[4][4], acc1[4][4];
            #pragma unroll
            for (int nt = 0; nt < 4; nt++)
                #pragma unroll
                for (int z = 0; z < 4; z++) { acc0[nt][z] = 0.f; acc1[nt][z] = 0.f; }

            // one k-step S (0..23): tp = S>>3, cb = S&7. B shared across both halves.
            #define KSTEP(S) do {                                                    \
                const int TP = (S) >> 3;                                             \
                const uint32_t cs = (uint32_t)(((S) & 7) * 2);                       \
                uint32_t bh[8], bl[8], ah[4], alr[4];                                \
                const uint32_t bsg = (uint32_t)(TP * 16) + cs + bd;                  \
                const uint32_t bo0 = brow0 + ((bsg ^ bj7) << 4);                     \
                const uint32_t bo1 = brow1 + ((bsg ^ bj7) << 4);                     \
                ldsm4(bh,     sb + SM_WHI + bo0);                                    \
                ldsm4(bh + 4, sb + SM_WHI + bo1);                                    \
                ldsm4(bl,     sb + SM_WLO + bo0);                                    \
                ldsm4(bl + 4, sb + SM_WLO + bo1);                                    \
                const uint32_t aoff0 = abase[0][TP] + (((cs + ad) ^ amask[0][TP]) << 4); \
                ldsm4(ah,  tHI + aoff0);                                             \
                ldsm4(alr, tLO + aoff0);                                             \
                _Pragma("unroll")                                                    \
                for (int nt = 0; nt < 4; nt++) {                                     \
                    mma16816(acc0[nt], ah,  bh + nt * 2);                            \
                    mma16816(acc0[nt], alr, bh + nt * 2);                            \
                    mma16816(acc0[nt], ah,  bl + nt * 2);                            \
                }                                                                    \
                const uint32_t aoff1 = abase[1][TP] + (((cs + ad) ^ amask[1][TP]) << 4); \
                ldsm4(ah,  tHI + aoff1);                                             \
                ldsm4(alr, tLO + aoff1);                                             \
                _Pragma("unroll")                                                    \
                for (int nt = 0; nt < 4; nt++) {                                     \
                    mma16816(acc1[nt], ah,  bh + nt * 2);                            \
                    mma16816(acc1[nt], alr, bh + nt * 2);                            \
                    mma16816(acc1[nt], ah,  bl + nt * 2);                            \
                }                                                                    \
            } while (0)

            if      (q == 0) { KSTEP(0);  KSTEP(1);  KSTEP(2);  KSTEP(3);  KSTEP(4);  KSTEP(5);  }
            else if (q == 1) { KSTEP(6);  KSTEP(7);  KSTEP(8);  KSTEP(9);  KSTEP(10); KSTEP(11); }
            else if (q == 2) { KSTEP(12); KSTEP(13); KSTEP(14); KSTEP(15); KSTEP(16); KSTEP(17); }
            else             { KSTEP(18); KSTEP(19); KSTEP(20); KSTEP(21); KSTEP(22); KSTEP(23); }
            #undef KSTEP

            // T reads done -> release buffer so producers refill during epilogue
            mbar_arrive(b ? barE1 : barE0);

            // ---- in-group 2-stage tree reduction (buf0 = red, buf1 = red+4096) ----
            // stage 1: q1 -> buf0, q3 -> buf1
            if (q == 1 || q == 3) {
                float4* dst = (float4*)(red + (q == 3 ? 4096 : 0));
                #pragma unroll
                for (int nt = 0; nt < 4; nt++) {
                    dst[nt * 32 + lane] =
                        make_float4(acc0[nt][0], acc0[nt][1], acc0[nt][2], acc0[nt][3]);
                    dst[(nt + 4) * 32 + lane] =
                        make_float4(acc1[nt][0], acc1[nt][1], acc1[nt][2], acc1[nt][3]);
                }
            }
            asm volatile("bar.sync %0, 128;" :: "r"(rbar) : "memory");
            // stage 2: q0 += buf0 ; q2 += buf1 then writes its sum back to buf1
            if (q == 0 || q == 2) {
                float4* srcb = (float4*)(red + (q == 2 ? 4096 : 0));
                #pragma unroll
                for (int nt = 0; nt < 4; nt++) {
                    float4 v0 = srcb[nt * 32 + lane];
                    float4 v1 = srcb[(nt + 4) * 32 + lane];
                    acc0[nt][0] += v0.x; acc0[nt][1] += v0.y;
                    acc0[nt][2] += v0.z; acc0[nt][3] += v0.w;
                    acc1[nt][0] += v1.x; acc1[nt][1] += v1.y;
                    acc1[nt][2] += v1.z; acc1[nt][3] += v1.w;
                }
                if (q == 2) {
                    float4* dst = (float4*)(red + 4096);
                    #pragma unroll
                    for (int nt = 0; nt < 4; nt++) {
                        dst[nt * 32 + lane] =
                            make_float4(acc0[nt][0], acc0[nt][1], acc0[nt][2], acc0[nt][3]);
                        dst[(nt + 4) * 32 + lane] =
                            make_float4(acc1[nt][0], acc1[nt][1], acc1[nt][2], acc1[nt][3]);
                    }
                }
            }
            asm volatile("bar.sync %0, 128;" :: "r"(rbar) : "memory");
            // stage 3: q0 += buf1, store with H-roll folded
            if (q == 0) {
                float4* srcb = (float4*)(red + 4096);
                #pragma unroll
                for (int nt = 0; nt < 4; nt++) {
                    float4 v0 = srcb[nt * 32 + lane];
                    float4 v1 = srcb[(nt + 4) * 32 + lane];
                    acc0[nt][0] += v0.x; acc0[nt][1] += v0.y;
                    acc0[nt][2] += v0.z; acc0[nt][3] += v0.w;
                    acc1[nt][0] += v1.x; acc1[nt][1] += v1.y;
                    acc1[nt][2] += v1.z; acc1[nt][3] += v1.w;
                }
                const int h  = hp * 2 + hsub;
                const int ho = (h + 1) % 56;
                float* ob = out + (size_t)n * 100352 + ho * 56;
                #pragma unroll
                for (int mt = 0; mt < 2; mt++) {
                    const int row0 = wm0 + mt * 16 + g;   // <= 55 always
                    const int row1 = row0 + 8;
                    float (*ac)[4] = mt ? acc1 : acc0;
                    #pragma unroll
                    for (int nt = 0; nt < 4; nt++) {
                        const int j = nt * 8 + tg * 2;
                        ob[(size_t)j * 3136 + row0]       = ac[nt][0];
                        ob[(size_t)(j + 1) * 3136 + row0] = ac[nt][1];
                        if (row1 < 56) {
                            ob[(size_t)j * 3136 + row1]       = ac[nt][2];
                            ob[(size_t)(j + 1) * 3136 + row1] = ac[nt][3];
                        }
                    }
                }
            }
            // protects buf0/buf1 against next tile's stage-1 writes
            asm volatile("bar.sync %0, 128;" :: "r"(rbar) : "memory");
        }
    } else {
        // ================= producers: fill T up to 2 tiles ahead =================
        int i = 0;
        for (int tt = t0; tt < NT; tt += NCTA, i++) {
            const int b = i & 1;
            if (i >= 2)
                mbar_wait(b ? barE1 : barE0, (uint32_t)(((i >> 1) - 1) & 1));
            produce_tile(x, smem,
                         b ? SM_T1H : SM_T0H, b ? SM_T1L : SM_T0L,
                         tt / 28, tt % 28, wid - 16, 8, lane);
            mbar_arrive(b ? barF1 : barF0);
        }
    }
}

extern "C" void kernel_launch(void* const* d_in, const int* in_sizes, int n_in,
                              void* d_out, int out_size) {
    const float* x = (const float*)d_in[0];   // (128,128,56,56)
    const float* w = (const float*)d_in[1];   // (32,3,128)
    float* out = (float*)d_out;               // (128,32,56,56)

    cudaFuncSetAttribute(shiftconv_g4, cudaFuncAttributeMaxDynamicSharedMemorySize, SM_TOTAL);
    shiftconv_g4<<<NCTA, THREADS, SM_TOTAL>>>(x, w, out);
}

// round 17
// speedup vs baseline: 2.3276x; 1.1121x over previous
#include <cuda_runtime.h>
#include <cuda_fp16.h>
#include <cstdint>

// y[n,j,h,w] = sum_{k,c} s[w+k][c] * wgt[j,k,c];  out[n,j,(h+1)%56,w] = y
//   s[u][c]: u==0||u==57 -> 0 ; u==1 -> x[...,55] (W-roll wrap) ; else x[...,u-2]
// Per tile (n, h-pair): D[128 m, 32 j] = A[128,384]*B[32,384]^T via mma.sync f16.
// X rounded to fp16 once (rel ~2.8e-4); W split Wh+Wl in fp16 -> 2 passes:
// y = sum X*(Wh+Wl).  768 threads / 24 warps. Consumers = warps 0-15 in 4 groups
// of 4: group owns 32m x 32j, warp q covers 6 of 24 k-steps (4-way k-split);
// per k-step 6 ldsm (4 B + 2 A) : 16 mma. In-group smem tree reduction.
// Producers = warps 16-23 fill double-buffered single-slab fp16 T; mbarrier
// handoff, consumers release T right after last ldsm.

#define NT      3584
#define NCTA    148
#define THREADS 768

#define SM_WHI  0u          // W hi fp16: [j][384], 768B rows, seg-swizzled
#define SM_WLO  24576u
#define SM_T0   49152u      // A fp16: [hs][64 u][128 c], 256B rows, seg-swizzled, 32KB
#define SM_T1   81920u
#define SM_RED  114688u     // 4 groups x 2 x 4KB tree-reduction buffers
#define SM_BARS 147456u     // full[2], empty[2] mbarriers
#define SM_TOTAL 147520

static __device__ __forceinline__ uint32_t s2u(const void* p) {
    uint32_t a;
    asm("{ .reg .u64 t; cvta.to.shared.u64 t, %1; cvt.u32.u64 %0, t; }" : "=r"(a) : "l"(p));
    return a;
}
// packed fp16x2: low half <- lo, high half <- hi (same operand order as proven bf2)
static __device__ __forceinline__ uint32_t hf2(float lo, float hi) {
    uint32_t r;
    asm("cvt.rn.f16x2.f32 %0, %1, %2;" : "=r"(r) : "f"(hi), "f"(lo));
    return r;
}
static __device__ __forceinline__ void ldsm4(uint32_t* r, uint32_t addr) {
    asm volatile("ldmatrix.sync.aligned.m8n8.x4.shared.b16 {%0,%1,%2,%3}, [%4];"
                 : "=r"(r[0]), "=r"(r[1]), "=r"(r[2]), "=r"(r[3]) : "r"(addr));
}
static __device__ __forceinline__ void mma16816(float* c, const uint32_t* a, const uint32_t* b) {
    asm volatile("mma.sync.aligned.m16n8k16.row.col.f32.f16.f16.f32 "
                 "{%0,%1,%2,%3}, {%4,%5,%6,%7}, {%8,%9}, {%0,%1,%2,%3};"
                 : "+f"(c[0]), "+f"(c[1]), "+f"(c[2]), "+f"(c[3])
                 : "r"(a[0]), "r"(a[1]), "r"(a[2]), "r"(a[3]), "r"(b[0]), "r"(b[1]));
}
static __device__ __forceinline__ void mbar_init(uint32_t bar, uint32_t cnt) {
    asm volatile("mbarrier.init.shared.b64 [%0], %1;" :: "r"(bar), "r"(cnt) : "memory");
}
static __device__ __forceinline__ void mbar_arrive(uint32_t bar) {
    asm volatile("mbarrier.arrive.shared.b64 _, [%0];" :: "r"(bar) : "memory");
}
static __device__ __forceinline__ void mbar_wait(uint32_t bar, uint32_t parity) {
    asm volatile(
        "{\n\t.reg .pred P;\n\t"
        "W%=:\n\t"
        "mbarrier.try_wait.parity.shared.b64 P, [%0], %1;\n\t"
        "@P bra.uni D%=;\n\t"
        "bra.uni W%=;\n\t"
        "D%=:\n\t}" :: "r"(bar), "r"(parity) : "memory");
}

// Produce one tile: x (global) -> single fp16 T slab, roll+pad folded into row u.
static __device__ __forceinline__ void produce_tile(const float* __restrict__ x,
                                                    char* smem, uint32_t dT,
                                                    int n, int hp, int warp0, int nwarps,
                                                    int lane) {
    const int cpl = lane >> 1;
    const int wc  = lane & 1;
    #pragma unroll 4
    for (int task = warp0; task < 56; task += nwarps) {
        const int hs  = task / 28;
        const int r   = task % 28;
        const int cpg = r / 7;
        const int wp  = r % 7;
        const int c   = cpg * 32 + cpl * 2;
        const int w0  = wp * 8 + wc * 4;
        const float* src = x + ((size_t)(n * 128 + c) * 56 + hp * 2 + hs) * 56 + w0;
        const float4 va = *(const float4*)src;
        const float4 vb = *(const float4*)(src + 3136);
        const float fa[4] = {va.x, va.y, va.z, va.w};
        const float fb[4] = {vb.x, vb.y, vb.z, vb.w};
        #pragma unroll
        for (int i = 0; i < 4; i++) {
            const int w = w0 + i;
            const int u = (w == 55) ? 1 : (w + 2);
            uint32_t seg = ((uint32_t)(c >> 3)) ^ (uint32_t)(u & 7);
            uint32_t off = (uint32_t)hs * 16384 + (uint32_t)u * 256
                           + (seg << 4) + ((uint32_t)(c & 7) << 1);
            *(uint32_t*)(smem + dT + off) = hf2(fa[i], fb[i]);
        }
    }
}

__global__ __launch_bounds__(THREADS, 1)
void shiftconv_h2(const float* __restrict__ x,
                  const float* __restrict__ wsrc,
                  float* __restrict__ out) {
    extern __shared__ char smem[];
    const uint32_t sb = s2u(smem);
    const int tid  = threadIdx.x;
    const int lane = tid & 31;
    const int wid  = tid >> 5;

    // ---- one-time: W hi/lo fp16 (seg-swizzled) ----
    for (int i = tid; i < 6144; i += THREADS) {
        int j = i / 192, kp = i % 192, k = kp * 2;
        float2 ab = *(const float2*)(wsrc + j * 384 + k);
        uint32_t hi = hf2(ab.x, ab.y);
        __half2 hh = *(__half2*)&hi;
        float ea = __low2float(hh);
        float eb = __high2float(hh);
        uint32_t lo = hf2(ab.x - ea, ab.y - eb);
        uint32_t seg = ((uint32_t)(k >> 3)) ^ (uint32_t)(j & 7);
        uint32_t off = (uint32_t)j * 768 + (seg << 4) + ((k & 7) << 1);
        *(uint32_t*)(smem + SM_WHI + off) = hi;
        *(uint32_t*)(smem + SM_WLO + off) = lo;
    }
    // ---- zero pad rows u in {0, 57..63}, both hs, both T slabs ----
    for (int i = tid; i < 2048; i += THREADS) {
        int slab = i >> 10;
        int rem  = i & 1023;
        int hs   = rem >> 9;
        int rw   = (rem >> 6) & 7;
        int u    = (rw == 0) ? 0 : (56 + rw);
        int wd   = rem & 63;
        *(uint32_t*)(smem + SM_T0 + (uint32_t)slab * 32768u + (uint32_t)hs * 16384
                     + (uint32_t)u * 256 + (uint32_t)wd * 4) = 0u;
    }
    // ---- mbarriers: full[b] <- producers (256 thr), empty[b] <- consumers (512 thr)
    const uint32_t barF0 = sb + SM_BARS,      barF1 = sb + SM_BARS + 8;
    const uint32_t barE0 = sb + SM_BARS + 16, barE1 = sb + SM_BARS + 24;
    if (tid == 0) {
        mbar_init(barF0, 256); mbar_init(barF1, 256);
        mbar_init(barE0, 512); mbar_init(barE1, 512);
    }
    __syncthreads();   // W, pad-zero, mbarrier init visible

    const int t0 = blockIdx.x;

    if (wid < 16) {
        // ==== consumers: 4 groups x 4 warps; group = 32m x 32j; warp = 6 k-steps ====
        const int grp = wid >> 2;             // 0..3 -> m sub-tile (32 rows)
        const int q   = wid & 3;              // k-quarter
        const int hsub = grp >> 1;
        const int wm0  = (grp & 1) * 32;
        const int g  = lane >> 2, tg = lane & 3;
        const int al = lane & 15;
        const uint32_t ad = (uint32_t)(lane >> 4);
        const int bj = (lane & 7) + ((lane >> 4) << 3);
        const uint32_t bd   = (uint32_t)((lane >> 3) & 1);
        const uint32_t bj7  = (uint32_t)(bj & 7);
        const uint32_t brow0 = (uint32_t)bj * 768;
        const uint32_t brow1 = (uint32_t)(bj + 16) * 768;
        uint32_t abase[2][3], amask[2][3];
        #pragma unroll
        for (int mt = 0; mt < 2; mt++)
            #pragma unroll
            for (int tp = 0; tp < 3; tp++) {
                int u = wm0 + mt * 16 + al + tp; if (u > 63) u = 63;
                abase[mt][tp] = (uint32_t)hsub * 16384 + (uint32_t)u * 256;
                amask[mt][tp] = (uint32_t)(u & 7);
            }
        char* red  = smem + SM_RED + (uint32_t)grp * 8192u;
        const int rbar = 1 + grp;

        int i = 0;
        for (int tt = t0; tt < NT; tt += NCTA, i++) {
            const int n = tt / 28, hp = tt % 28;
            const int b = i & 1;
            mbar_wait(b ? barF1 : barF0, (uint32_t)((i >> 1) & 1));

            const uint32_t tA = sb + (b ? SM_T1 : SM_T0);
            float acc0[4][4], acc1[4][4];
            #pragma unroll
            for (int nt = 0; nt < 4; nt++)
                #pragma unroll
                for (int z = 0; z < 4; z++) { acc0[nt][z] = 0.f; acc1[nt][z] = 0.f; }

            // one k-step S (0..23): tp = S>>3, cb = S&7. B shared across both halves.
            #define KSTEP(S) do {                                                    \
                const int TP = (S) >> 3;                                             \
                const uint32_t cs = (uint32_t)(((S) & 7) * 2);                       \
                uint32_t bh[8], bl[8], a[4];                                         \
                const uint32_t bsg = (uint32_t)(TP * 16) + cs + bd;                  \
                const uint32_t bo0 = brow0 + ((bsg ^ bj7) << 4);                     \
                const uint32_t bo1 = brow1 + ((bsg ^ bj7) << 4);                     \
                ldsm4(bh,     sb + SM_WHI + bo0);                                    \
                ldsm4(bh + 4, sb + SM_WHI + bo1);                                    \
                ldsm4(bl,     sb + SM_WLO + bo0);                                    \
                ldsm4(bl + 4, sb + SM_WLO + bo1);                                    \
                const uint32_t aoff0 = abase[0][TP] + (((cs + ad) ^ amask[0][TP]) << 4); \
                ldsm4(a, tA + aoff0);                                                \
                _Pragma("unroll")                                                    \
                for (int nt = 0; nt < 4; nt++) {                                     \
                    mma16816(acc0[nt], a, bh + nt * 2);                              \
                    mma16816(acc0[nt], a, bl + nt * 2);                              \
                }                                                                    \
                const uint32_t aoff1 = abase[1][TP] + (((cs + ad) ^ amask[1][TP]) << 4); \
                ldsm4(a, tA + aoff1);                                                \
                _Pragma("unroll")                                                    \
                for (int nt = 0; nt < 4; nt++) {                                     \
                    mma16816(acc1[nt], a, bh + nt * 2);                              \
                    mma16816(acc1[nt], a, bl + nt * 2);                              \
                }                                                                    \
            } while (0)

            if      (q == 0) { KSTEP(0);  KSTEP(1);  KSTEP(2);  KSTEP(3);  KSTEP(4);  KSTEP(5);  }
            else if (q == 1) { KSTEP(6);  KSTEP(7);  KSTEP(8);  KSTEP(9);  KSTEP(10); KSTEP(11); }
            else if (q == 2) { KSTEP(12); KSTEP(13); KSTEP(14); KSTEP(15); KSTEP(16); KSTEP(17); }
            else             { KSTEP(18); KSTEP(19); KSTEP(20); KSTEP(21); KSTEP(22); KSTEP(23); }
            #undef KSTEP

            // T reads done -> release buffer so producers refill during epilogue
            mbar_arrive(b ? barE1 : barE0);

            // ---- in-group 2-stage tree reduction (buf0 = red, buf1 = red+4096) ----
            if (q == 1 || q == 3) {
                float4* dst = (float4*)(red + (q == 3 ? 4096 : 0));
                #pragma unroll
                for (int nt = 0; nt < 4; nt++) {
                    dst[nt * 32 + lane] =
                        make_float4(acc0[nt][0], acc0[nt][1], acc0[nt][2], acc0[nt][3]);
                    dst[(nt + 4) * 32 + lane] =
                        make_float4(acc1[nt][0], acc1[nt][1], acc1[nt][2], acc1[nt][3]);
                }
            }
            asm volatile("bar.sync %0, 128;" :: "r"(rbar) : "memory");
            if (q == 0 || q == 2) {
                float4* srcb = (float4*)(red + (q == 2 ? 4096 : 0));
                #pragma unroll
                for (int nt = 0; nt < 4; nt++) {
                    float4 v0 = srcb[nt * 32 + lane];
                    float4 v1 = srcb[(nt + 4) * 32 + lane];
                    acc0[nt][0] += v0.x; acc0[nt][1] += v0.y;
                    acc0[nt][2] += v0.z; acc0[nt][3] += v0.w;
                    acc1[nt][0] += v1.x; acc1[nt][1] += v1.y;
                    acc1[nt][2] += v1.z; acc1[nt][3] += v1.w;
                }
                if (q == 2) {
                    float4* dst = (float4*)(red + 4096);
                    #pragma unroll
                    for (int nt = 0; nt < 4; nt++) {
                        dst[nt * 32 + lane] =
                            make_float4(acc0[nt][0], acc0[nt][1], acc0[nt][2], acc0[nt][3]);
                        dst[(nt + 4) * 32 + lane] =
                            make_float4(acc1[nt][0], acc1[nt][1], acc1[nt][2], acc1[nt][3]);
                    }
                }
            }
            asm volatile("bar.sync %0, 128;" :: "r"(rbar) : "memory");
            if (q == 0) {
                float4* srcb = (float4*)(red + 4096);
                #pragma unroll
                for (int nt = 0; nt < 4; nt++) {
                    float4 v0 = srcb[nt * 32 + lane];
                    float4 v1 = srcb[(nt + 4) * 32 + lane];
                    acc0[nt][0] += v0.x; acc0[nt][1] += v0.y;
                    acc0[nt][2] += v0.z; acc0[nt][3] += v0.w;
                    acc1[nt][0] += v1.x; acc1[nt][1] += v1.y;
                    acc1[nt][2] += v1.z; acc1[nt][3] += v1.w;
                }
                const int h  = hp * 2 + hsub;
                const int ho = (h + 1) % 56;
                float* ob = out + (size_t)n * 100352 + ho * 56;
                #pragma unroll
                for (int mt = 0; mt < 2; mt++) {
                    const int row0 = wm0 + mt * 16 + g;   // <= 55 always
                    const int row1 = row0 + 8;
                    float (*ac)[4] = mt ? acc1 : acc0;
                    #pragma unroll
                    for (int nt = 0; nt < 4; nt++) {
                        const int j = nt * 8 + tg * 2;
                        ob[(size_t)j * 3136 + row0]       = ac[nt][0];
                        ob[(size_t)(j + 1) * 3136 + row0] = ac[nt][1];
                        if (row1 < 56) {
                            ob[(size_t)j * 3136 + row1]       = ac[nt][2];
                            ob[(size_t)(j + 1) * 3136 + row1] = ac[nt][3];
                        }
                    }
                }
            }
            // protects buf0/buf1 against next tile's stage-1 writes
            asm volatile("bar.sync %0, 128;" :: "r"(rbar) : "memory");
        }
    } else {
        // ================= producers: fill T up to 2 tiles ahead =================
        int i = 0;
        for (int tt = t0; tt < NT; tt += NCTA, i++) {
            const int b = i & 1;
            if (i >= 2)
                mbar_wait(b ? barE1 : barE0, (uint32_t)(((i >> 1) - 1) & 1));
            produce_tile(x, smem, b ? SM_T1 : SM_T0,
                         tt / 28, tt % 28, wid - 16, 8, lane);
            mbar_arrive(b ? barF1 : barF0);
        }
    }
}

extern "C" void kernel_launch(void* const* d_in, const int* in_sizes, int n_in,
                              void* d_out, int out_size) {
    const float* x = (const float*)d_in[0];   // (128,128,56,56)
    const float* w = (const float*)d_in[1];   // (32,3,128)
    float* out = (float*)d_out;               // (128,32,56,56)

    cudaFuncSetAttribute(shiftconv_h2, cudaFuncAttributeMaxDynamicSharedMemorySize, SM_TOTAL);
    shiftconv_h2<<<NCTA, THREADS, SM_TOTAL>>>(x, w, out);
}